// round 5
// baseline (speedup 1.0000x reference)
#include <cuda_runtime.h>
#include <cuda_fp16.h>
#include <mma.h>
#include <math.h>

using namespace nvcuda;

#define NN 100000
#define EE 1600000
#define GG 32
#define INC 100
#define HC 64
#define EPS 1e-5f
#define NBLK 98            // ceil(NN/1024)
#define FPS 1048576.0f     // 2^20 fixed-point scale for degree

// ---------------- scratch ----------------
__device__ unsigned long long g_packed[NN];  // (count<<32) | fixedpoint(sum|w|)
__device__ float  g_dinv [NN];
__device__ int    g_cnt_e[NN];
__device__ int    g_rowst[NN];
__device__ int    g_bsum [128];
__device__ int    g_pos  [EE];
__device__ int    g_srcs [EE];
__device__ float  g_wn   [EE];
__device__ __half g_bufH [(size_t)NN * HC];  // GEMM output (messages)
__device__ __half g_bufB [(size_t)NN * HC];  // prop output (next GEMM input)
__device__ float  g_pool [GG * HC];
__device__ float  g_gcnt [GG];

// ---------------- init ----------------
__global__ void init_kernel() {
    int i = blockIdx.x * blockDim.x + threadIdx.x;
    if (i < NN) g_packed[i] = 0ull;
    if (i < GG * HC) g_pool[i] = 0.f;
    if (i < GG) g_gcnt[i] = 0.f;
}

// degree + slot reservation in ONE 64-bit atomic per edge
__global__ void edge_accum_kernel(const int* __restrict__ dst,
                                  const float* __restrict__ ew) {
    int e = blockIdx.x * blockDim.x + threadIdx.x;
    if (e >= EE) return;
    int d = dst[e];
    unsigned int wfix = (unsigned int)(fabsf(ew[e]) * FPS + 0.5f);
    unsigned long long pk = (1ull << 32) | (unsigned long long)wfix;
    unsigned long long old = atomicAdd(&g_packed[d], pk);
    g_pos[e] = (int)(old >> 32);
}

// ---------------- 2-level exclusive scan of counts -> g_rowst ----------------
__global__ void scan_block_kernel() {
    __shared__ int sh[1024];
    int tid = threadIdx.x;
    int i = blockIdx.x * 1024 + tid;
    int v = (i < NN) ? (int)(g_packed[i] >> 32) : 0;
    sh[tid] = v;
    __syncthreads();
    #pragma unroll
    for (int off = 1; off < 1024; off <<= 1) {
        int t = (tid >= off) ? sh[tid - off] : 0;
        __syncthreads();
        sh[tid] += t;
        __syncthreads();
    }
    if (i < NN) g_rowst[i] = sh[tid] - v;
    if (tid == 1023) g_bsum[blockIdx.x] = sh[1023];
}

__global__ void scan_bsum_kernel() {
    __shared__ int sh[128];
    int tid = threadIdx.x;
    int v = (tid < NBLK) ? g_bsum[tid] : 0;
    sh[tid] = v;
    __syncthreads();
    #pragma unroll
    for (int off = 1; off < 128; off <<= 1) {
        int t = (tid >= off) ? sh[tid - off] : 0;
        __syncthreads();
        sh[tid] += t;
        __syncthreads();
    }
    if (tid < NBLK) g_bsum[tid] = sh[tid] - v;
}

__global__ void add_offsets_kernel() {
    int i = blockIdx.x * blockDim.x + threadIdx.x;
    if (i >= NN) return;
    unsigned long long pk = g_packed[i];
    int cnt = (int)(pk >> 32);
    float deg = (float)(unsigned int)(pk & 0xffffffffull) * (1.0f / FPS) + 1.0f;
    g_rowst[i] += g_bsum[i >> 10];
    g_cnt_e[i] = cnt;
    g_dinv[i]  = rsqrtf(deg);
}

// ---------------- scatter edges into CSR (no atomics) ----------------
__global__ void scatter_kernel(const int* __restrict__ src,
                               const int* __restrict__ dst,
                               const float* __restrict__ ew) {
    int e = blockIdx.x * blockDim.x + threadIdx.x;
    if (e >= EE) return;
    int s = src[e], d = dst[e];
    int pos = g_rowst[d] + g_pos[e];
    g_srcs[pos] = s;
    g_wn[pos]   = g_dinv[s] * fabsf(ew[e]) * g_dinv[d];
}

// ---------------- tensor-core GEMM: Yh[N,64] = X[N,DIN] @ W[DIN,64] ----------------
// 128x64 tile, 8 warps, whole K in smem, wmma 16x16x16 fp16->fp32.
template <int DIN, typename TIN>
__global__ void __launch_bounds__(256) gemm_mma_kernel(const TIN* __restrict__ X,
                                                       const float* __restrict__ W,
                                                       __half* __restrict__ Yh) {
    constexpr int KP = (DIN + 15) & ~15;
    constexpr int XB = 128 * KP * 2;
    constexpr int WB = KP * 64 * 2;
    constexpr int SB = (XB + WB) > (128 * 64 * 4) ? (XB + WB) : (128 * 64 * 4);
    __shared__ __align__(16) char sm[SB];
    __half* Xs = (__half*)sm;
    __half* Ws = (__half*)(sm + XB);
    float*  St = (float*)sm;             // overlaid staging (used after sync)

    const int t = threadIdx.x;
    const int warp = t >> 5;
    const int base = blockIdx.x * 128;

    // W (DIN x 64 f32) -> Ws (KP x 64 half), zero-pad rows k >= DIN
    for (int i = t; i < KP * 32; i += 256) {
        int k = i >> 5;
        int c = (i & 31) << 1;
        __half2 h = __floats2half2_rn(0.f, 0.f);
        if (k < DIN) {
            float2 w = *(const float2*)(W + (size_t)k * 64 + c);
            h = __floats2half2_rn(w.x, w.y);
        }
        *(__half2*)(Ws + k * 64 + c) = h;
    }
    // X tile (128 x DIN) -> Xs (128 x KP half), convert if fp32 input
    constexpr int KP2 = KP / 2;
    for (int i = t; i < 128 * KP2; i += 256) {
        int n = i / KP2;
        int k = (i - n * KP2) << 1;
        __half2 h = __floats2half2_rn(0.f, 0.f);
        int nn = base + n;
        if (nn < NN && k < DIN) {
            if constexpr (sizeof(TIN) == 4) {
                float2 v = *(const float2*)((const float*)X + (size_t)nn * DIN + k);
                h = __floats2half2_rn(v.x, v.y);
            } else {
                h = *(const __half2*)((const __half*)X + (size_t)nn * DIN + k);
            }
        }
        *(__half2*)(Xs + n * KP + k) = h;
    }
    __syncthreads();

    wmma::fragment<wmma::accumulator, 16, 16, 16, float> acc[4];
    #pragma unroll
    for (int nb = 0; nb < 4; nb++) wmma::fill_fragment(acc[nb], 0.f);

    #pragma unroll
    for (int k = 0; k < KP; k += 16) {
        wmma::fragment<wmma::matrix_a, 16, 16, 16, __half, wmma::row_major> a;
        wmma::load_matrix_sync(a, Xs + warp * 16 * KP + k, KP);
        #pragma unroll
        for (int nb = 0; nb < 4; nb++) {
            wmma::fragment<wmma::matrix_b, 16, 16, 16, __half, wmma::row_major> bf;
            wmma::load_matrix_sync(bf, Ws + k * 64 + nb * 16, 64);
            wmma::mma_sync(acc[nb], a, bf, acc[nb]);
        }
    }
    __syncthreads();   // all Xs/Ws reads done before overlay

    #pragma unroll
    for (int nb = 0; nb < 4; nb++)
        wmma::store_matrix_sync(St + warp * 16 * 64 + nb * 16, acc[nb], 64,
                                wmma::mem_row_major);
    __syncthreads();

    for (int i = t; i < 128 * 32; i += 256) {
        int n = i >> 5;
        int c = (i & 31) << 1;
        int nn = base + n;
        if (nn < NN) {
            float2 f = *(const float2*)(St + n * 64 + c);
            *(__half2*)(Yh + (size_t)nn * 64 + c) = __floats2half2_rn(f.x, f.y);
        }
    }
}

// ---------------- fused CSR gather-reduce + BN + ReLU (+ pooling) ----------------
// half-warp (16 lanes) per dst node; lane owns 4 channels (half4 load, fp32 acc)
__device__ __forceinline__ void acc_half4(float4& a, float w, uint2 u) {
    float2 f0 = __half22float2(*reinterpret_cast<__half2*>(&u.x));
    float2 f1 = __half22float2(*reinterpret_cast<__half2*>(&u.y));
    a.x = fmaf(w, f0.x, a.x); a.y = fmaf(w, f0.y, a.y);
    a.z = fmaf(w, f1.x, a.z); a.w = fmaf(w, f1.y, a.w);
}

template <bool LAST>
__global__ void prop_fused_kernel(const __half* __restrict__ H,
                                  const float* __restrict__ b,
                                  const float* __restrict__ g,
                                  const float* __restrict__ bt,
                                  const float* __restrict__ rm,
                                  const float* __restrict__ rv,
                                  const int* __restrict__ batch,
                                  __half* __restrict__ out) {
    const int warp  = blockIdx.x * (blockDim.x >> 5) + (threadIdx.x >> 5);
    const int lane  = threadIdx.x & 31;
    const int half  = lane >> 4;
    const int sub   = lane & 15;
    const int node  = (warp << 1) + half;
    if (node >= NN) return;
    const int ch = sub << 2;
    const unsigned hmask = half ? 0xffff0000u : 0x0000ffffu;

    const int s0 = g_rowst[node];
    const int s1 = s0 + g_cnt_e[node];

    float4 a0 = {0,0,0,0}, a1 = {0,0,0,0}, a2 = {0,0,0,0}, a3 = {0,0,0,0};

    for (int j = s0; j < s1; j += 16) {
        const int m = min(16, s1 - j);
        int sv = 0; float wv = 0.f;
        if (sub < m) { sv = g_srcs[j + sub]; wv = g_wn[j + sub]; }
        int k = 0;
        for (; k + 4 <= m; k += 4) {
            int   sA = __shfl_sync(hmask, sv, k,     16);
            float wA = __shfl_sync(hmask, wv, k,     16);
            int   sB = __shfl_sync(hmask, sv, k + 1, 16);
            float wB = __shfl_sync(hmask, wv, k + 1, 16);
            int   sC = __shfl_sync(hmask, sv, k + 2, 16);
            float wC = __shfl_sync(hmask, wv, k + 2, 16);
            int   sD = __shfl_sync(hmask, sv, k + 3, 16);
            float wD = __shfl_sync(hmask, wv, k + 3, 16);
            uint2 uA = *(const uint2*)(H + (size_t)sA * 64 + ch);
            uint2 uB = *(const uint2*)(H + (size_t)sB * 64 + ch);
            uint2 uC = *(const uint2*)(H + (size_t)sC * 64 + ch);
            uint2 uD = *(const uint2*)(H + (size_t)sD * 64 + ch);
            acc_half4(a0, wA, uA);
            acc_half4(a1, wB, uB);
            acc_half4(a2, wC, uC);
            acc_half4(a3, wD, uD);
        }
        for (; k < m; k++) {
            int   sA = __shfl_sync(hmask, sv, k, 16);
            float wA = __shfl_sync(hmask, wv, k, 16);
            uint2 uA = *(const uint2*)(H + (size_t)sA * 64 + ch);
            acc_half4(a0, wA, uA);
        }
    }

    // combine + self-loop + bias + BN + ReLU
    const float dv  = g_dinv[node];
    const float dv2 = dv * dv;
    uint2 uh = *(const uint2*)(H + (size_t)node * 64 + ch);
    float2 h0 = __half22float2(*reinterpret_cast<__half2*>(&uh.x));
    float2 h1 = __half22float2(*reinterpret_cast<__half2*>(&uh.y));
    float4 bb  = *(const float4*)(b  + ch);
    float4 gg  = *(const float4*)(g  + ch);
    float4 btv = *(const float4*)(bt + ch);
    float4 rmv = *(const float4*)(rm + ch);
    float4 rvv = *(const float4*)(rv + ch);

    float sx = (a0.x + a1.x) + (a2.x + a3.x) + h0.x * dv2 + bb.x;
    float sy = (a0.y + a1.y) + (a2.y + a3.y) + h0.y * dv2 + bb.y;
    float sz = (a0.z + a1.z) + (a2.z + a3.z) + h1.x * dv2 + bb.z;
    float sw = (a0.w + a1.w) + (a2.w + a3.w) + h1.y * dv2 + bb.w;

    sx = fmaxf((sx - rmv.x) * (gg.x * rsqrtf(rvv.x + EPS)) + btv.x, 0.f);
    sy = fmaxf((sy - rmv.y) * (gg.y * rsqrtf(rvv.y + EPS)) + btv.y, 0.f);
    sz = fmaxf((sz - rmv.z) * (gg.z * rsqrtf(rvv.z + EPS)) + btv.z, 0.f);
    sw = fmaxf((sw - rmv.w) * (gg.w * rsqrtf(rvv.w + EPS)) + btv.w, 0.f);

    if (LAST) {
        // only pooling consumes the last layer's output
        int gr = batch[node];
        float4 r = make_float4(sx, sy, sz, sw);
        atomicAdd((float4*)(g_pool + gr * 64 + ch), r);
        if (sub == 0) atomicAdd(&g_gcnt[gr], 1.0f);
    } else {
        uint2 o;
        __half2 lo = __floats2half2_rn(sx, sy);
        __half2 hi = __floats2half2_rn(sz, sw);
        o.x = *(unsigned int*)&lo;
        o.y = *(unsigned int*)&hi;
        *(uint2*)(out + (size_t)node * 64 + ch) = o;
    }
}

// ---------------- final output ----------------
__global__ void out_kernel(float* __restrict__ out) {
    int gr = blockIdx.x;
    int c  = threadIdx.x;
    float s  = g_pool[gr * 64 + (c & 63)];
    float cc = fmaxf(g_gcnt[gr], 1.0f);
    out[gr * 128 + c] = (c < 64) ? s / cc : s;
}

// ---------------- launch ----------------
extern "C" void kernel_launch(void* const* d_in, const int* in_sizes, int n_in,
                              void* d_out, int out_size) {
    const float* x     = (const float*)d_in[0];
    const int*   ei    = (const int*)  d_in[1];
    const float* ew    = (const float*)d_in[2];
    const int*   batch = (const int*)  d_in[3];
    const int*   src   = ei;
    const int*   dst   = ei + EE;
    float* out = (float*)d_out;

    const float *Wl[3], *bl[3], *gl[3], *btl[3], *rml[3], *rvl[3];
    for (int l = 0; l < 3; l++) {
        Wl[l]  = (const float*)d_in[4 + 6 * l + 0];
        bl[l]  = (const float*)d_in[4 + 6 * l + 1];
        gl[l]  = (const float*)d_in[4 + 6 * l + 2];
        btl[l] = (const float*)d_in[4 + 6 * l + 3];
        rml[l] = (const float*)d_in[4 + 6 * l + 4];
        rvl[l] = (const float*)d_in[4 + 6 * l + 5];
    }

    __half *bufH, *bufB;
    cudaGetSymbolAddress((void**)&bufH, g_bufH);
    cudaGetSymbolAddress((void**)&bufB, g_bufB);

    const int T = 256;
    const int nGrid = (NN + T - 1) / T;
    const int eGrid = (EE + T - 1) / T;

    // ---- CSR build (once; reused by all 3 layers) ----
    init_kernel<<<nGrid, T>>>();
    edge_accum_kernel<<<eGrid, T>>>(dst, ew);
    scan_block_kernel<<<NBLK, 1024>>>();
    scan_bsum_kernel<<<1, 128>>>();
    add_offsets_kernel<<<nGrid, T>>>();
    scatter_kernel<<<eGrid, T>>>(src, dst, ew);

    const int gemmGrid = (NN + 127) / 128;
    const int propGrid = (NN / 2 + 7) / 8;   // 8 warps/block, 2 nodes/warp

    // ---- layer 0 ----
    gemm_mma_kernel<INC, float><<<gemmGrid, 256>>>(x, Wl[0], bufH);
    prop_fused_kernel<false><<<propGrid, 256>>>(bufH, bl[0], gl[0], btl[0],
                                                rml[0], rvl[0], batch, bufB);
    // ---- layer 1 ----
    gemm_mma_kernel<HC, __half><<<gemmGrid, 256>>>(bufB, Wl[1], bufH);
    prop_fused_kernel<false><<<propGrid, 256>>>(bufH, bl[1], gl[1], btl[1],
                                                rml[1], rvl[1], batch, bufB);
    // ---- layer 2 (pooling only, no H' store) ----
    gemm_mma_kernel<HC, __half><<<gemmGrid, 256>>>(bufB, Wl[2], bufH);
    prop_fused_kernel<true><<<propGrid, 256>>>(bufH, bl[2], gl[2], btl[2],
                                               rml[2], rvl[2], batch, bufB);

    out_kernel<<<GG, 128>>>(out);
}

// round 6
// speedup vs baseline: 1.5026x; 1.5026x over previous
#include <cuda_runtime.h>
#include <cuda_fp16.h>
#include <math.h>

#define NN 100000
#define EE 1600000
#define GG 32
#define INC 100
#define HC 64
#define EPS 1e-5f
#define NBLK 98            // ceil(NN/1024)
#define FPS 1048576.0f     // 2^20 fixed-point scale for degree

// ---------------- scratch (zero-initialized at module load; kernels that
// consume one-shot state re-zero it afterwards so graph replays are exact) ----
__device__ unsigned long long g_packed[NN];  // (count<<32) | fixedpoint(sum|w|)
__device__ float  g_dinv [NN];
__device__ int    g_cnt_e[NN];
__device__ int    g_rowst[NN];
__device__ int    g_bsum [128];
__device__ int    g_pos  [EE];
__device__ int    g_srcs [EE];
__device__ float  g_wn   [EE];
__device__ __half g_bufH [(size_t)NN * HC];  // GEMM output (messages)
__device__ __half g_bufB [(size_t)NN * HC];  // prop output (next GEMM input)
__device__ float  g_pool [GG * HC];
__device__ float  g_gcnt [GG];

// ---------------- degree + slot reservation (g_packed must be 0 on entry) ----
__global__ void edge_accum_kernel(const int* __restrict__ dst,
                                  const float* __restrict__ ew) {
    int e = blockIdx.x * blockDim.x + threadIdx.x;
    if (e >= EE) return;
    int d = dst[e];
    unsigned int wfix = (unsigned int)(fabsf(ew[e]) * FPS + 0.5f);
    unsigned long long pk = (1ull << 32) | (unsigned long long)wfix;
    unsigned long long old = atomicAdd(&g_packed[d], pk);
    g_pos[e] = (int)(old >> 32);
}

// ---------------- block-level scan of counts ----------------
__global__ void scan_block_kernel() {
    __shared__ int sh[1024];
    int tid = threadIdx.x;
    int i = blockIdx.x * 1024 + tid;
    int v = (i < NN) ? (int)(g_packed[i] >> 32) : 0;
    sh[tid] = v;
    __syncthreads();
    #pragma unroll
    for (int off = 1; off < 1024; off <<= 1) {
        int t = (tid >= off) ? sh[tid - off] : 0;
        __syncthreads();
        sh[tid] += t;
        __syncthreads();
    }
    if (i < NN) g_rowst[i] = sh[tid] - v;
    if (tid == 1023) g_bsum[blockIdx.x] = sh[1023];
}

// ---------------- finalize offsets: inline bsum scan + dinv + state reset ----
__global__ void add_offsets_kernel() {          // 128 threads per block
    __shared__ int sh[128];
    __shared__ int pre[128];
    int t = threadIdx.x;
    int v = (t < NBLK) ? g_bsum[t] : 0;
    sh[t] = v;
    __syncthreads();
    #pragma unroll
    for (int off = 1; off < 128; off <<= 1) {
        int tmp = (t >= off) ? sh[t - off] : 0;
        __syncthreads();
        sh[t] += tmp;
        __syncthreads();
    }
    pre[t] = sh[t] - v;                          // exclusive block offsets
    __syncthreads();

    int i = blockIdx.x * blockDim.x + t;
    if (i >= NN) return;
    unsigned long long pk = g_packed[i];
    g_packed[i] = 0ull;                          // reset for next replay
    int cnt = (int)(pk >> 32);
    float deg = (float)(unsigned int)(pk & 0xffffffffull) * (1.0f / FPS) + 1.0f;
    g_rowst[i] += pre[i >> 10];
    g_cnt_e[i] = cnt;
    g_dinv[i]  = rsqrtf(deg);
}

// ---------------- scatter edges into CSR (no atomics) ----------------
__global__ void scatter_kernel(const int* __restrict__ src,
                               const int* __restrict__ dst,
                               const float* __restrict__ ew) {
    int e = blockIdx.x * blockDim.x + threadIdx.x;
    if (e >= EE) return;
    int s = src[e], d = dst[e];
    int pos = g_rowst[d] + g_pos[e];
    g_srcs[pos] = s;
    g_wn[pos]   = g_dinv[s] * fabsf(ew[e]) * g_dinv[d];
}

// ---------------- GEMM: Yh[N,64](half) = X[N,DIN] @ W[DIN,64] ----------------
// 128x64 tile, 256 threads, 8x4 micro-tile, K-chunks of 32. fp32 FFMA.
template <int DIN, typename TIN>
__global__ void __launch_bounds__(256) gemm_kernel(const TIN* __restrict__ X,
                                                   const float* __restrict__ W,
                                                   __half* __restrict__ Yh) {
    __shared__ float Xs[32 * 132];   // [kk][n], padded
    __shared__ float Ws[32 * 64];    // [kk][c]
    const int t  = threadIdx.x;
    const int tx = t & 15;           // channel quad
    const int ty = t >> 4;           // node octet
    const int base = blockIdx.x * 128;

    float4 acc[8];
    #pragma unroll
    for (int r = 0; r < 8; r++) acc[r] = make_float4(0.f, 0.f, 0.f, 0.f);

    for (int k0 = 0; k0 < DIN; k0 += 32) {
        const int kc = (DIN - k0 < 32) ? (DIN - k0) : 32;
        // X tile: 128 nodes x 32 k, transposed into Xs[kk][n]
        #pragma unroll
        for (int it = 0; it < 4; it++) {
            int i  = t + it * 256;
            int n  = i >> 3;
            int kq = (i & 7) << 2;
            float4 v = {0.f, 0.f, 0.f, 0.f};
            int nn = base + n;
            if (nn < NN && kq < kc) {
                if constexpr (sizeof(TIN) == 4) {
                    v = *(const float4*)((const float*)X + (size_t)nn * DIN + k0 + kq);
                } else {
                    uint2 u = *(const uint2*)((const __half*)X + (size_t)nn * DIN + k0 + kq);
                    float2 f0 = __half22float2(*reinterpret_cast<__half2*>(&u.x));
                    float2 f1 = __half22float2(*reinterpret_cast<__half2*>(&u.y));
                    v = make_float4(f0.x, f0.y, f1.x, f1.y);
                }
            }
            Xs[(kq + 0) * 132 + n] = v.x;
            Xs[(kq + 1) * 132 + n] = v.y;
            Xs[(kq + 2) * 132 + n] = v.z;
            Xs[(kq + 3) * 132 + n] = v.w;
        }
        // W tile
        #pragma unroll
        for (int it = 0; it < 2; it++) {
            int i  = t + it * 256;
            int kk = i >> 4;
            int cq = (i & 15) << 2;
            float4 w = {0.f, 0.f, 0.f, 0.f};
            if (kk < kc)
                w = *(const float4*)(W + (size_t)(k0 + kk) * 64 + cq);
            *(float4*)&Ws[kk * 64 + cq] = w;
        }
        __syncthreads();

        for (int kk = 0; kk < kc; kk++) {
            float4 b  = *(const float4*)&Ws[kk * 64 + (tx << 2)];
            float4 aL = *(const float4*)&Xs[kk * 132 + (ty << 3)];
            float4 aH = *(const float4*)&Xs[kk * 132 + (ty << 3) + 4];
            acc[0].x = fmaf(aL.x, b.x, acc[0].x); acc[0].y = fmaf(aL.x, b.y, acc[0].y);
            acc[0].z = fmaf(aL.x, b.z, acc[0].z); acc[0].w = fmaf(aL.x, b.w, acc[0].w);
            acc[1].x = fmaf(aL.y, b.x, acc[1].x); acc[1].y = fmaf(aL.y, b.y, acc[1].y);
            acc[1].z = fmaf(aL.y, b.z, acc[1].z); acc[1].w = fmaf(aL.y, b.w, acc[1].w);
            acc[2].x = fmaf(aL.z, b.x, acc[2].x); acc[2].y = fmaf(aL.z, b.y, acc[2].y);
            acc[2].z = fmaf(aL.z, b.z, acc[2].z); acc[2].w = fmaf(aL.z, b.w, acc[2].w);
            acc[3].x = fmaf(aL.w, b.x, acc[3].x); acc[3].y = fmaf(aL.w, b.y, acc[3].y);
            acc[3].z = fmaf(aL.w, b.z, acc[3].z); acc[3].w = fmaf(aL.w, b.w, acc[3].w);
            acc[4].x = fmaf(aH.x, b.x, acc[4].x); acc[4].y = fmaf(aH.x, b.y, acc[4].y);
            acc[4].z = fmaf(aH.x, b.z, acc[4].z); acc[4].w = fmaf(aH.x, b.w, acc[4].w);
            acc[5].x = fmaf(aH.y, b.x, acc[5].x); acc[5].y = fmaf(aH.y, b.y, acc[5].y);
            acc[5].z = fmaf(aH.y, b.z, acc[5].z); acc[5].w = fmaf(aH.y, b.w, acc[5].w);
            acc[6].x = fmaf(aH.z, b.x, acc[6].x); acc[6].y = fmaf(aH.z, b.y, acc[6].y);
            acc[6].z = fmaf(aH.z, b.z, acc[6].z); acc[6].w = fmaf(aH.z, b.w, acc[6].w);
            acc[7].x = fmaf(aH.w, b.x, acc[7].x); acc[7].y = fmaf(aH.w, b.y, acc[7].y);
            acc[7].z = fmaf(aH.w, b.z, acc[7].z); acc[7].w = fmaf(aH.w, b.w, acc[7].w);
        }
        __syncthreads();
    }

    const int c0 = tx << 2;
    #pragma unroll
    for (int r = 0; r < 8; r++) {
        int nn = base + (ty << 3) + r;
        if (nn < NN) {
            __half2 lo = __floats2half2_rn(acc[r].x, acc[r].y);
            __half2 hi = __floats2half2_rn(acc[r].z, acc[r].w);
            uint2 u;
            u.x = *(unsigned int*)&lo;
            u.y = *(unsigned int*)&hi;
            *(uint2*)(Yh + (size_t)nn * 64 + c0) = u;
        }
    }
}

// ---------------- fused CSR gather-reduce + BN + ReLU (+ pooling) ----------------
__device__ __forceinline__ void acc_half4(float4& a, float w, uint2 u) {
    float2 f0 = __half22float2(*reinterpret_cast<__half2*>(&u.x));
    float2 f1 = __half22float2(*reinterpret_cast<__half2*>(&u.y));
    a.x = fmaf(w, f0.x, a.x); a.y = fmaf(w, f0.y, a.y);
    a.z = fmaf(w, f1.x, a.z); a.w = fmaf(w, f1.y, a.w);
}

template <bool LAST>
__global__ void prop_fused_kernel(const __half* __restrict__ H,
                                  const float* __restrict__ b,
                                  const float* __restrict__ g,
                                  const float* __restrict__ bt,
                                  const float* __restrict__ rm,
                                  const float* __restrict__ rv,
                                  const int* __restrict__ batch,
                                  __half* __restrict__ out) {
    const int warp  = blockIdx.x * (blockDim.x >> 5) + (threadIdx.x >> 5);
    const int lane  = threadIdx.x & 31;
    const int half  = lane >> 4;
    const int sub   = lane & 15;
    const int node  = (warp << 1) + half;
    if (node >= NN) return;
    const int ch = sub << 2;
    const unsigned hmask = half ? 0xffff0000u : 0x0000ffffu;

    const int s0 = g_rowst[node];
    const int s1 = s0 + g_cnt_e[node];

    float4 a0 = {0,0,0,0}, a1 = {0,0,0,0}, a2 = {0,0,0,0}, a3 = {0,0,0,0};

    for (int j = s0; j < s1; j += 16) {
        const int m = min(16, s1 - j);
        int sv = 0; float wv = 0.f;
        if (sub < m) { sv = g_srcs[j + sub]; wv = g_wn[j + sub]; }
        int k = 0;
        for (; k + 4 <= m; k += 4) {
            int   sA = __shfl_sync(hmask, sv, k,     16);
            float wA = __shfl_sync(hmask, wv, k,     16);
            int   sB = __shfl_sync(hmask, sv, k + 1, 16);
            float wB = __shfl_sync(hmask, wv, k + 1, 16);
            int   sC = __shfl_sync(hmask, sv, k + 2, 16);
            float wC = __shfl_sync(hmask, wv, k + 2, 16);
            int   sD = __shfl_sync(hmask, sv, k + 3, 16);
            float wD = __shfl_sync(hmask, wv, k + 3, 16);
            uint2 uA = *(const uint2*)(H + (size_t)sA * 64 + ch);
            uint2 uB = *(const uint2*)(H + (size_t)sB * 64 + ch);
            uint2 uC = *(const uint2*)(H + (size_t)sC * 64 + ch);
            uint2 uD = *(const uint2*)(H + (size_t)sD * 64 + ch);
            acc_half4(a0, wA, uA);
            acc_half4(a1, wB, uB);
            acc_half4(a2, wC, uC);
            acc_half4(a3, wD, uD);
        }
        for (; k < m; k++) {
            int   sA = __shfl_sync(hmask, sv, k, 16);
            float wA = __shfl_sync(hmask, wv, k, 16);
            uint2 uA = *(const uint2*)(H + (size_t)sA * 64 + ch);
            acc_half4(a0, wA, uA);
        }
    }

    // combine + self-loop + bias + BN + ReLU
    const float dv  = g_dinv[node];
    const float dv2 = dv * dv;
    uint2 uh = *(const uint2*)(H + (size_t)node * 64 + ch);
    float2 h0 = __half22float2(*reinterpret_cast<__half2*>(&uh.x));
    float2 h1 = __half22float2(*reinterpret_cast<__half2*>(&uh.y));
    float4 bb  = *(const float4*)(b  + ch);
    float4 gg  = *(const float4*)(g  + ch);
    float4 btv = *(const float4*)(bt + ch);
    float4 rmv = *(const float4*)(rm + ch);
    float4 rvv = *(const float4*)(rv + ch);

    float sx = (a0.x + a1.x) + (a2.x + a3.x) + h0.x * dv2 + bb.x;
    float sy = (a0.y + a1.y) + (a2.y + a3.y) + h0.y * dv2 + bb.y;
    float sz = (a0.z + a1.z) + (a2.z + a3.z) + h1.x * dv2 + bb.z;
    float sw = (a0.w + a1.w) + (a2.w + a3.w) + h1.y * dv2 + bb.w;

    sx = fmaxf((sx - rmv.x) * (gg.x * rsqrtf(rvv.x + EPS)) + btv.x, 0.f);
    sy = fmaxf((sy - rmv.y) * (gg.y * rsqrtf(rvv.y + EPS)) + btv.y, 0.f);
    sz = fmaxf((sz - rmv.z) * (gg.z * rsqrtf(rvv.z + EPS)) + btv.z, 0.f);
    sw = fmaxf((sw - rmv.w) * (gg.w * rsqrtf(rvv.w + EPS)) + btv.w, 0.f);

    if (LAST) {
        int gr = batch[node];
        float4 r = make_float4(sx, sy, sz, sw);
        atomicAdd((float4*)(g_pool + gr * 64 + ch), r);
        if (sub == 0) atomicAdd(&g_gcnt[gr], 1.0f);
    } else {
        uint2 o;
        __half2 lo = __floats2half2_rn(sx, sy);
        __half2 hi = __floats2half2_rn(sz, sw);
        o.x = *(unsigned int*)&lo;
        o.y = *(unsigned int*)&hi;
        *(uint2*)(out + (size_t)node * 64 + ch) = o;
    }
}

// ---------------- final output (+ pool reset for next replay) ----------------
__global__ void out_kernel(float* __restrict__ out) {
    int gr = blockIdx.x;        // 0..31
    int c  = threadIdx.x;       // 0..127
    float s  = g_pool[gr * 64 + (c & 63)];
    float cc = fmaxf(g_gcnt[gr], 1.0f);
    out[gr * 128 + c] = (c < 64) ? s / cc : s;
    __syncthreads();
    if (c < 64) g_pool[gr * 64 + c] = 0.f;
    if (c == 64) g_gcnt[gr] = 0.f;
}

// ---------------- launch ----------------
extern "C" void kernel_launch(void* const* d_in, const int* in_sizes, int n_in,
                              void* d_out, int out_size) {
    const float* x     = (const float*)d_in[0];
    const int*   ei    = (const int*)  d_in[1];
    const float* ew    = (const float*)d_in[2];
    const int*   batch = (const int*)  d_in[3];
    const int*   src   = ei;
    const int*   dst   = ei + EE;
    float* out = (float*)d_out;

    const float *Wl[3], *bl[3], *gl[3], *btl[3], *rml[3], *rvl[3];
    for (int l = 0; l < 3; l++) {
        Wl[l]  = (const float*)d_in[4 + 6 * l + 0];
        bl[l]  = (const float*)d_in[4 + 6 * l + 1];
        gl[l]  = (const float*)d_in[4 + 6 * l + 2];
        btl[l] = (const float*)d_in[4 + 6 * l + 3];
        rml[l] = (const float*)d_in[4 + 6 * l + 4];
        rvl[l] = (const float*)d_in[4 + 6 * l + 5];
    }

    __half *bufH, *bufB;
    cudaGetSymbolAddress((void**)&bufH, g_bufH);
    cudaGetSymbolAddress((void**)&bufB, g_bufB);

    const int T = 256;
    const int eGrid = (EE + T - 1) / T;

    // ---- CSR build (once; reused by all 3 layers) ----
    edge_accum_kernel<<<eGrid, T>>>(dst, ew);
    scan_block_kernel<<<NBLK, 1024>>>();
    add_offsets_kernel<<<(NN + 127) / 128, 128>>>();
    scatter_kernel<<<eGrid, T>>>(src, dst, ew);

    const int gemmGrid = (NN + 127) / 128;
    const int propGrid = (NN / 2 + 7) / 8;   // 8 warps/block, 2 nodes/warp

    // ---- layer 0 ----
    gemm_kernel<INC, float><<<gemmGrid, 256>>>(x, Wl[0], bufH);
    prop_fused_kernel<false><<<propGrid, 256>>>(bufH, bl[0], gl[0], btl[0],
                                                rml[0], rvl[0], batch, bufB);
    // ---- layer 1 ----
    gemm_kernel<HC, __half><<<gemmGrid, 256>>>(bufB, Wl[1], bufH);
    prop_fused_kernel<false><<<propGrid, 256>>>(bufH, bl[1], gl[1], btl[1],
                                                rml[1], rvl[1], batch, bufB);
    // ---- layer 2 (pooling only, no H' store) ----
    gemm_kernel<HC, __half><<<gemmGrid, 256>>>(bufB, Wl[2], bufH);
    prop_fused_kernel<true><<<propGrid, 256>>>(bufH, bl[2], gl[2], btl[2],
                                               rml[2], rvl[2], batch, bufB);

    out_kernel<<<GG, 128>>>(out);
}

// round 7
// speedup vs baseline: 1.5382x; 1.0237x over previous
#include <cuda_runtime.h>
#include <cuda_fp16.h>
#include <math.h>

#define NN 100000
#define EE 1600000
#define GG 32
#define INC 100
#define HC 64
#define EPS 1e-5f
#define NBLK 98            // ceil(NN/1024)
#define FPS 1048576.0f     // 2^20 fixed-point scale for degree

// ---------------- scratch (zero-initialized at module load; kernels that
// consume one-shot state re-zero it afterwards so graph replays are exact) ----
__device__ unsigned long long g_packed[NN];  // (count<<32) | fixedpoint(sum|w|)
__device__ float  g_dinv [NN];
__device__ int    g_cnt_e[NN];
__device__ int    g_rowst[NN];
__device__ int    g_bsum [128];
__device__ int    g_pos  [EE];
__device__ unsigned long long g_csr[EE];     // packed (|ew| bits << 32) | src
__device__ __half g_bufH [(size_t)NN * HC];  // GEMM output, pre-scaled by dinv
__device__ __half g_bufB [(size_t)NN * HC];  // prop output (next GEMM input)
__device__ float  g_pool [GG * HC];
__device__ float  g_gcnt [GG];

// ---------------- degree + slot reservation (g_packed must be 0 on entry) ----
__global__ void edge_accum_kernel(const int* __restrict__ dst,
                                  const float* __restrict__ ew) {
    int e = blockIdx.x * blockDim.x + threadIdx.x;
    if (e >= EE) return;
    int d = dst[e];
    unsigned int wfix = (unsigned int)(fabsf(ew[e]) * FPS + 0.5f);
    unsigned long long pk = (1ull << 32) | (unsigned long long)wfix;
    unsigned long long old = atomicAdd(&g_packed[d], pk);
    g_pos[e] = (int)(old >> 32);
}

// ---------------- block-level scan of counts ----------------
__global__ void scan_block_kernel() {
    __shared__ int sh[1024];
    int tid = threadIdx.x;
    int i = blockIdx.x * 1024 + tid;
    int v = (i < NN) ? (int)(g_packed[i] >> 32) : 0;
    sh[tid] = v;
    __syncthreads();
    #pragma unroll
    for (int off = 1; off < 1024; off <<= 1) {
        int t = (tid >= off) ? sh[tid - off] : 0;
        __syncthreads();
        sh[tid] += t;
        __syncthreads();
    }
    if (i < NN) g_rowst[i] = sh[tid] - v;
    if (tid == 1023) g_bsum[blockIdx.x] = sh[1023];
}

// ---------------- finalize offsets: inline bsum scan + dinv + state reset ----
__global__ void add_offsets_kernel() {          // 128 threads per block
    __shared__ int sh[128];
    __shared__ int pre[128];
    int t = threadIdx.x;
    int v = (t < NBLK) ? g_bsum[t] : 0;
    sh[t] = v;
    __syncthreads();
    #pragma unroll
    for (int off = 1; off < 128; off <<= 1) {
        int tmp = (t >= off) ? sh[t - off] : 0;
        __syncthreads();
        sh[t] += tmp;
        __syncthreads();
    }
    pre[t] = sh[t] - v;                          // exclusive block offsets
    __syncthreads();

    int i = blockIdx.x * blockDim.x + t;
    if (i >= NN) return;
    unsigned long long pk = g_packed[i];
    g_packed[i] = 0ull;                          // reset for next replay
    int cnt = (int)(pk >> 32);
    float deg = (float)(unsigned int)(pk & 0xffffffffull) * (1.0f / FPS) + 1.0f;
    g_rowst[i] += pre[i >> 10];
    g_cnt_e[i] = cnt;
    g_dinv[i]  = rsqrtf(deg);
}

// ---------------- scatter edges into CSR (streaming + 1 random 8B store) ----
__global__ void scatter_kernel(const int* __restrict__ src,
                               const int* __restrict__ dst,
                               const float* __restrict__ ew) {
    int e = blockIdx.x * blockDim.x + threadIdx.x;
    if (e >= EE) return;
    int s = src[e], d = dst[e];
    int pos = g_rowst[d] + g_pos[e];
    unsigned int wbits = __float_as_uint(fabsf(ew[e]));
    g_csr[pos] = ((unsigned long long)wbits << 32) | (unsigned int)s;
}

// ---------------- GEMM: Yh[N,64](half) = (X[N,DIN] @ W[DIN,64]) * dinv[row] ----
// 128x64 tile, 256 threads, 8x4 micro-tile, K-chunks of 32. fp32 FFMA.
template <int DIN, typename TIN>
__global__ void __launch_bounds__(256) gemm_kernel(const TIN* __restrict__ X,
                                                   const float* __restrict__ W,
                                                   __half* __restrict__ Yh) {
    __shared__ float Xs[32 * 132];   // [kk][n], padded
    __shared__ float Ws[32 * 64];    // [kk][c]
    const int t  = threadIdx.x;
    const int tx = t & 15;           // channel quad
    const int ty = t >> 4;           // node octet
    const int base = blockIdx.x * 128;

    float4 acc[8];
    #pragma unroll
    for (int r = 0; r < 8; r++) acc[r] = make_float4(0.f, 0.f, 0.f, 0.f);

    for (int k0 = 0; k0 < DIN; k0 += 32) {
        const int kc = (DIN - k0 < 32) ? (DIN - k0) : 32;
        // X tile: 128 nodes x 32 k, transposed into Xs[kk][n]
        #pragma unroll
        for (int it = 0; it < 4; it++) {
            int i  = t + it * 256;
            int n  = i >> 3;
            int kq = (i & 7) << 2;
            float4 v = {0.f, 0.f, 0.f, 0.f};
            int nn = base + n;
            if (nn < NN && kq < kc) {
                if constexpr (sizeof(TIN) == 4) {
                    v = *(const float4*)((const float*)X + (size_t)nn * DIN + k0 + kq);
                } else {
                    uint2 u = *(const uint2*)((const __half*)X + (size_t)nn * DIN + k0 + kq);
                    float2 f0 = __half22float2(*reinterpret_cast<__half2*>(&u.x));
                    float2 f1 = __half22float2(*reinterpret_cast<__half2*>(&u.y));
                    v = make_float4(f0.x, f0.y, f1.x, f1.y);
                }
            }
            Xs[(kq + 0) * 132 + n] = v.x;
            Xs[(kq + 1) * 132 + n] = v.y;
            Xs[(kq + 2) * 132 + n] = v.z;
            Xs[(kq + 3) * 132 + n] = v.w;
        }
        // W tile
        #pragma unroll
        for (int it = 0; it < 2; it++) {
            int i  = t + it * 256;
            int kk = i >> 4;
            int cq = (i & 15) << 2;
            float4 w = {0.f, 0.f, 0.f, 0.f};
            if (kk < kc)
                w = *(const float4*)(W + (size_t)(k0 + kk) * 64 + cq);
            *(float4*)&Ws[kk * 64 + cq] = w;
        }
        __syncthreads();

        for (int kk = 0; kk < kc; kk++) {
            float4 b  = *(const float4*)&Ws[kk * 64 + (tx << 2)];
            float4 aL = *(const float4*)&Xs[kk * 132 + (ty << 3)];
            float4 aH = *(const float4*)&Xs[kk * 132 + (ty << 3) + 4];
            acc[0].x = fmaf(aL.x, b.x, acc[0].x); acc[0].y = fmaf(aL.x, b.y, acc[0].y);
            acc[0].z = fmaf(aL.x, b.z, acc[0].z); acc[0].w = fmaf(aL.x, b.w, acc[0].w);
            acc[1].x = fmaf(aL.y, b.x, acc[1].x); acc[1].y = fmaf(aL.y, b.y, acc[1].y);
            acc[1].z = fmaf(aL.y, b.z, acc[1].z); acc[1].w = fmaf(aL.y, b.w, acc[1].w);
            acc[2].x = fmaf(aL.z, b.x, acc[2].x); acc[2].y = fmaf(aL.z, b.y, acc[2].y);
            acc[2].z = fmaf(aL.z, b.z, acc[2].z); acc[2].w = fmaf(aL.z, b.w, acc[2].w);
            acc[3].x = fmaf(aL.w, b.x, acc[3].x); acc[3].y = fmaf(aL.w, b.y, acc[3].y);
            acc[3].z = fmaf(aL.w, b.z, acc[3].z); acc[3].w = fmaf(aL.w, b.w, acc[3].w);
            acc[4].x = fmaf(aH.x, b.x, acc[4].x); acc[4].y = fmaf(aH.x, b.y, acc[4].y);
            acc[4].z = fmaf(aH.x, b.z, acc[4].z); acc[4].w = fmaf(aH.x, b.w, acc[4].w);
            acc[5].x = fmaf(aH.y, b.x, acc[5].x); acc[5].y = fmaf(aH.y, b.y, acc[5].y);
            acc[5].z = fmaf(aH.y, b.z, acc[5].z); acc[5].w = fmaf(aH.y, b.w, acc[5].w);
            acc[6].x = fmaf(aH.z, b.x, acc[6].x); acc[6].y = fmaf(aH.z, b.y, acc[6].y);
            acc[6].z = fmaf(aH.z, b.z, acc[6].z); acc[6].w = fmaf(aH.z, b.w, acc[6].w);
            acc[7].x = fmaf(aH.w, b.x, acc[7].x); acc[7].y = fmaf(aH.w, b.y, acc[7].y);
            acc[7].z = fmaf(aH.w, b.z, acc[7].z); acc[7].w = fmaf(aH.w, b.w, acc[7].w);
        }
        __syncthreads();
    }

    const int c0 = tx << 2;
    #pragma unroll
    for (int r = 0; r < 8; r++) {
        int nn = base + (ty << 3) + r;
        if (nn < NN) {
            float dv = g_dinv[nn];            // pre-scale row by dinv
            __half2 lo = __floats2half2_rn(acc[r].x * dv, acc[r].y * dv);
            __half2 hi = __floats2half2_rn(acc[r].z * dv, acc[r].w * dv);
            uint2 u;
            u.x = *(unsigned int*)&lo;
            u.y = *(unsigned int*)&hi;
            *(uint2*)(Yh + (size_t)nn * 64 + c0) = u;
        }
    }
}

// ---------------- fused CSR gather-reduce + BN + ReLU (+ pooling) ----------------
// out[d] = relu(BN(dinv[d]*(sum |w|*Ht[s] + Ht[d]) + b))
__device__ __forceinline__ void acc_half4(float4& a, float w, uint2 u) {
    float2 f0 = __half22float2(*reinterpret_cast<__half2*>(&u.x));
    float2 f1 = __half22float2(*reinterpret_cast<__half2*>(&u.y));
    a.x = fmaf(w, f0.x, a.x); a.y = fmaf(w, f0.y, a.y);
    a.z = fmaf(w, f1.x, a.z); a.w = fmaf(w, f1.y, a.w);
}

template <bool LAST>
__global__ void prop_fused_kernel(const __half* __restrict__ H,
                                  const float* __restrict__ b,
                                  const float* __restrict__ g,
                                  const float* __restrict__ bt,
                                  const float* __restrict__ rm,
                                  const float* __restrict__ rv,
                                  const int* __restrict__ batch,
                                  __half* __restrict__ out) {
    const int warp  = blockIdx.x * (blockDim.x >> 5) + (threadIdx.x >> 5);
    const int lane  = threadIdx.x & 31;
    const int half  = lane >> 4;
    const int sub   = lane & 15;
    const int node  = (warp << 1) + half;
    if (node >= NN) return;
    const int ch = sub << 2;
    const unsigned hmask = half ? 0xffff0000u : 0x0000ffffu;

    const int s0 = g_rowst[node];
    const int s1 = s0 + g_cnt_e[node];

    float4 a0 = {0,0,0,0}, a1 = {0,0,0,0}, a2 = {0,0,0,0}, a3 = {0,0,0,0};

    for (int j = s0; j < s1; j += 16) {
        const int m = min(16, s1 - j);
        int sv = 0; float wv = 0.f;
        if (sub < m) {
            uint2 c = *(const uint2*)&g_csr[j + sub];
            sv = (int)c.x;
            wv = __uint_as_float(c.y);
        }
        int k = 0;
        for (; k + 4 <= m; k += 4) {
            int   sA = __shfl_sync(hmask, sv, k,     16);
            float wA = __shfl_sync(hmask, wv, k,     16);
            int   sB = __shfl_sync(hmask, sv, k + 1, 16);
            float wB = __shfl_sync(hmask, wv, k + 1, 16);
            int   sC = __shfl_sync(hmask, sv, k + 2, 16);
            float wC = __shfl_sync(hmask, wv, k + 2, 16);
            int   sD = __shfl_sync(hmask, sv, k + 3, 16);
            float wD = __shfl_sync(hmask, wv, k + 3, 16);
            uint2 uA = *(const uint2*)(H + (size_t)sA * 64 + ch);
            uint2 uB = *(const uint2*)(H + (size_t)sB * 64 + ch);
            uint2 uC = *(const uint2*)(H + (size_t)sC * 64 + ch);
            uint2 uD = *(const uint2*)(H + (size_t)sD * 64 + ch);
            acc_half4(a0, wA, uA);
            acc_half4(a1, wB, uB);
            acc_half4(a2, wC, uC);
            acc_half4(a3, wD, uD);
        }
        for (; k < m; k++) {
            int   sA = __shfl_sync(hmask, sv, k, 16);
            float wA = __shfl_sync(hmask, wv, k, 16);
            uint2 uA = *(const uint2*)(H + (size_t)sA * 64 + ch);
            acc_half4(a0, wA, uA);
        }
    }

    // combine: self term Ht[d] has implicit weight 1
    const float dv = g_dinv[node];
    uint2 uh = *(const uint2*)(H + (size_t)node * 64 + ch);
    float2 h0 = __half22float2(*reinterpret_cast<__half2*>(&uh.x));
    float2 h1 = __half22float2(*reinterpret_cast<__half2*>(&uh.y));
    float4 bb  = *(const float4*)(b  + ch);
    float4 gg  = *(const float4*)(g  + ch);
    float4 btv = *(const float4*)(bt + ch);
    float4 rmv = *(const float4*)(rm + ch);
    float4 rvv = *(const float4*)(rv + ch);

    float sx = fmaf(((a0.x + a1.x) + (a2.x + a3.x)) + h0.x, dv, bb.x);
    float sy = fmaf(((a0.y + a1.y) + (a2.y + a3.y)) + h0.y, dv, bb.y);
    float sz = fmaf(((a0.z + a1.z) + (a2.z + a3.z)) + h1.x, dv, bb.z);
    float sw = fmaf(((a0.w + a1.w) + (a2.w + a3.w)) + h1.y, dv, bb.w);

    sx = fmaxf((sx - rmv.x) * (gg.x * rsqrtf(rvv.x + EPS)) + btv.x, 0.f);
    sy = fmaxf((sy - rmv.y) * (gg.y * rsqrtf(rvv.y + EPS)) + btv.y, 0.f);
    sz = fmaxf((sz - rmv.z) * (gg.z * rsqrtf(rvv.z + EPS)) + btv.z, 0.f);
    sw = fmaxf((sw - rmv.w) * (gg.w * rsqrtf(rvv.w + EPS)) + btv.w, 0.f);

    if (LAST) {
        int gr = batch[node];
        float4 r = make_float4(sx, sy, sz, sw);
        atomicAdd((float4*)(g_pool + gr * 64 + ch), r);
        if (sub == 0) atomicAdd(&g_gcnt[gr], 1.0f);
    } else {
        uint2 o;
        __half2 lo = __floats2half2_rn(sx, sy);
        __half2 hi = __floats2half2_rn(sz, sw);
        o.x = *(unsigned int*)&lo;
        o.y = *(unsigned int*)&hi;
        *(uint2*)(out + (size_t)node * 64 + ch) = o;
    }
}

// ---------------- final output (+ pool reset for next replay) ----------------
__global__ void out_kernel(float* __restrict__ out) {
    int gr = blockIdx.x;        // 0..31
    int c  = threadIdx.x;       // 0..127
    float s  = g_pool[gr * 64 + (c & 63)];
    float cc = fmaxf(g_gcnt[gr], 1.0f);
    out[gr * 128 + c] = (c < 64) ? s / cc : s;
    __syncthreads();
    if (c < 64) g_pool[gr * 64 + c] = 0.f;
    if (c == 64) g_gcnt[gr] = 0.f;
}

// ---------------- launch ----------------
extern "C" void kernel_launch(void* const* d_in, const int* in_sizes, int n_in,
                              void* d_out, int out_size) {
    const float* x     = (const float*)d_in[0];
    const int*   ei    = (const int*)  d_in[1];
    const float* ew    = (const float*)d_in[2];
    const int*   batch = (const int*)  d_in[3];
    const int*   src   = ei;
    const int*   dst   = ei + EE;
    float* out = (float*)d_out;

    const float *Wl[3], *bl[3], *gl[3], *btl[3], *rml[3], *rvl[3];
    for (int l = 0; l < 3; l++) {
        Wl[l]  = (const float*)d_in[4 + 6 * l + 0];
        bl[l]  = (const float*)d_in[4 + 6 * l + 1];
        gl[l]  = (const float*)d_in[4 + 6 * l + 2];
        btl[l] = (const float*)d_in[4 + 6 * l + 3];
        rml[l] = (const float*)d_in[4 + 6 * l + 4];
        rvl[l] = (const float*)d_in[4 + 6 * l + 5];
    }

    __half *bufH, *bufB;
    cudaGetSymbolAddress((void**)&bufH, g_bufH);
    cudaGetSymbolAddress((void**)&bufB, g_bufB);

    const int T = 256;
    const int eGrid = (EE + T - 1) / T;

    // ---- CSR build (once; reused by all 3 layers) ----
    edge_accum_kernel<<<eGrid, T>>>(dst, ew);
    scan_block_kernel<<<NBLK, 1024>>>();
    add_offsets_kernel<<<(NN + 127) / 128, 128>>>();
    scatter_kernel<<<eGrid, T>>>(src, dst, ew);

    const int gemmGrid = (NN + 127) / 128;
    const int propGrid = (NN / 2 + 7) / 8;   // 8 warps/block, 2 nodes/warp

    // ---- layer 0 ----
    gemm_kernel<INC, float><<<gemmGrid, 256>>>(x, Wl[0], bufH);
    prop_fused_kernel<false><<<propGrid, 256>>>(bufH, bl[0], gl[0], btl[0],
                                                rml[0], rvl[0], batch, bufB);
    // ---- layer 1 ----
    gemm_kernel<HC, __half><<<gemmGrid, 256>>>(bufB, Wl[1], bufH);
    prop_fused_kernel<false><<<propGrid, 256>>>(bufH, bl[1], gl[1], btl[1],
                                                rml[1], rvl[1], batch, bufB);
    // ---- layer 2 (pooling only, no H' store) ----
    gemm_kernel<HC, __half><<<gemmGrid, 256>>>(bufB, Wl[2], bufH);
    prop_fused_kernel<true><<<propGrid, 256>>>(bufH, bl[2], gl[2], btl[2],
                                               rml[2], rvl[2], batch, bufB);

    out_kernel<<<GG, 128>>>(out);
}